// round 13
// baseline (speedup 1.0000x reference)
#include <cuda_runtime.h>

// NashCascadeNetwork: 8 layers x 524288 buckets, 8 spigots/bucket.
// Inputs (metadata order): H[NB] f32, S[NB,8,2] f32, theta[NB*8] f32, precip[1] f32
// Output (f32): [ H_new(NB) | s_q(NB*8) | network_outflow(1) ]
//
// R9 structure (the 90.0us best: one bucket per thread, 256-thread blocks,
// shfl_up carry + one cheap barrier) with a single change: __launch_bounds__
// minBlocks=7 to cap registers at 36 (was 40), lifting occupancy 48->56
// warps/SM. All else byte-identical.

#define NB          4194304
#define NS          8
#define BPL         524288                   // buckets in last layer
#define NTHREADS    256
#define BPB         256                      // buckets per block (1 per thread)
#define NWARPS      (NTHREADS / 32)          // 8
#define NGRID       (NB / BPB)               // 16384
#define FIRST_LAST  ((NB - BPL) / BPB)       // 14336
#define NLASTBLK    (BPL / BPB)              // 2048
#define OUT_SQ_OFF  NB
#define OUT_SCALAR  (NB * (NS + 1))          // 37748736

__device__ double   g_partials[NLASTBLK];
__device__ unsigned g_count = 0;

// q = theta * sqrt(2*9.8*h) * 0.5*(tanh(h)+1) * area,  h = max(0, H - height)
// 0.5*(tanh(h)+1) == sigmoid(2h) == 1/(1+exp(-2h))  -> EX2 + RCP (err ~1e-7)
__device__ __forceinline__ float spigot_q(float Hb, float sh, float sa, float th) {
    float h = fmaxf(0.0f, Hb - sh);
    float e = __expf(-2.0f * h);
    float mod;
    asm("rcp.approx.f32 %0, %1;" : "=f"(mod) : "f"(1.0f + e));
    float s;
    asm("sqrt.approx.f32 %0, %1;" : "=f"(s) : "f"(19.6f * h));
    return th * s * mod * sa;
}

__global__ __launch_bounds__(NTHREADS, 7)
void nash_main(const float* __restrict__ H,
               const float4* __restrict__ S4,     // [NB*4]
               const float4* __restrict__ T4,     // [NB*2]
               const float* __restrict__ precip,
               float* __restrict__ out)
{
    float*  Hn  = out;
    float4* SQ4 = (float4*)(out + OUT_SQ_OFF);

    const int tid  = threadIdx.x;
    const int lane = tid & 31;
    const int warp = tid >> 5;
    const int b    = blockIdx.x * BPB + tid;

    // ---- front-batched streaming loads: whole bucket in 6x128b + 1x32b ----
    const float  Hb = H[b];
    const float4 s0 = __ldcs(&S4[(size_t)b * 4 + 0]);
    const float4 s1 = __ldcs(&S4[(size_t)b * 4 + 1]);
    const float4 s2 = __ldcs(&S4[(size_t)b * 4 + 2]);
    const float4 s3 = __ldcs(&S4[(size_t)b * 4 + 3]);
    const float4 t0 = __ldcs(&T4[(size_t)b * 2 + 0]);
    const float4 t1 = __ldcs(&T4[(size_t)b * 2 + 1]);

    // ---- block-boundary bucket (b0-1): warp 0, lanes 0-7, one spigot each ----
    float pe = 0.0f;
    if (warp == 0) {
        if (blockIdx.x != 0 && lane < 8) {
            const int    bp = blockIdx.x * BPB - 1;
            const float  Hp = H[bp];
            const float2 sp = ((const float2*)S4)[(size_t)bp * 8 + lane];
            const float  tp = ((const float*)T4)[(size_t)bp * 8 + lane];
            pe = spigot_q(Hp, sp.x, sp.y, tp);
        }
        pe += __shfl_xor_sync(0xffffffffu, pe, 1);
        pe += __shfl_xor_sync(0xffffffffu, pe, 2);
        pe += __shfl_xor_sync(0xffffffffu, pe, 4);   // lane 0 = full sum
    }

    // ---- 8 spigots, all in-register ----
    const float q0 = spigot_q(Hb, s0.x, s0.y, t0.x);
    const float q1 = spigot_q(Hb, s0.z, s0.w, t0.y);
    const float q2 = spigot_q(Hb, s1.x, s1.y, t0.z);
    const float q3 = spigot_q(Hb, s1.z, s1.w, t0.w);
    const float q4 = spigot_q(Hb, s2.x, s2.y, t1.x);
    const float q5 = spigot_q(Hb, s2.z, s2.w, t1.y);
    const float q6 = spigot_q(Hb, s3.x, s3.y, t1.z);
    const float q7 = spigot_q(Hb, s3.z, s3.w, t1.w);

    __stcs(&SQ4[(size_t)b * 2 + 0], make_float4(q0, q1, q2, q3));
    __stcs(&SQ4[(size_t)b * 2 + 1], make_float4(q4, q5, q6, q7));

    const float ob = ((q0 + q1) + (q2 + q3)) + ((q4 + q5) + (q6 + q7));

    // ---- inflow[b] = outflow[b-1]: shfl_up + smem warp carries ----
    float inflow = __shfl_up_sync(0xffffffffu, ob, 1);
    __shared__ float s_carry[NWARPS];
    if (lane == 31) s_carry[warp] = ob;
    __syncthreads();
    if (lane == 0)
        inflow = (warp == 0)
               ? ((blockIdx.x == 0) ? __ldg(precip) : pe)
               : s_carry[warp - 1];
    __stcs(&Hn[b], Hb + inflow - ob);

    // ---- last-layer network-outflow reduction (last 12.5% of blocks) ----
    if (blockIdx.x >= FIRST_LAST) {
        double a = (double)ob;
        a += __shfl_xor_sync(0xffffffffu, a, 16);
        a += __shfl_xor_sync(0xffffffffu, a, 8);
        a += __shfl_xor_sync(0xffffffffu, a, 4);
        a += __shfl_xor_sync(0xffffffffu, a, 2);
        a += __shfl_xor_sync(0xffffffffu, a, 1);

        __shared__ double sd[NWARPS];
        __shared__ bool   s_last;
        if (tid == 0) s_last = false;
        if (lane == 0) sd[warp] = a;
        __syncthreads();
        if (tid == 0) {
            double bs = ((sd[0] + sd[1]) + (sd[2] + sd[3]))
                      + ((sd[4] + sd[5]) + (sd[6] + sd[7]));
            g_partials[blockIdx.x - FIRST_LAST] = bs;
            __threadfence();
            unsigned t = atomicAdd(&g_count, 1u);
            if (t == NLASTBLK - 1) s_last = true;
        }
        __syncthreads();

        if (s_last) {
            // Last block alive: fixed-order reduction (bit-deterministic).
            __threadfence();
            double acc = 0.0;
            #pragma unroll 4
            for (int i = tid; i < NLASTBLK; i += NTHREADS)
                acc += g_partials[i];
            __shared__ double sm[NTHREADS];
            sm[tid] = acc;
            __syncthreads();
            #pragma unroll
            for (int s = NTHREADS / 2; s > 0; s >>= 1) {
                if (tid < s) sm[tid] += sm[tid + s];
                __syncthreads();
            }
            if (tid == 0) {
                out[OUT_SCALAR] = (float)sm[0];
                g_count = 0;                     // reset for graph replay
            }
        }
    }
}

extern "C" void kernel_launch(void* const* d_in, const int* in_sizes, int n_in,
                              void* d_out, int out_size) {
    const float*  H      = (const float*)d_in[0];
    const float4* S4     = (const float4*)d_in[1];
    const float4* T4     = (const float4*)d_in[2];
    const float*  precip = (const float*)d_in[3];

    nash_main<<<NGRID, NTHREADS>>>(H, S4, T4, precip, (float*)d_out);
}

// round 14
// speedup vs baseline: 1.0411x; 1.0411x over previous
#include <cuda_runtime.h>

// NashCascadeNetwork: 8 layers x 524288 buckets, 8 spigots/bucket.
// Inputs (metadata order): H[NB] f32, S[NB,8,2] f32, theta[NB*8] f32, precip[1] f32
// Output (f32): [ H_new(NB) | s_q(NB*8) | network_outflow(1) ]
//
// R9 structure (one bucket per thread, 256-thread blocks, shfl_up carry +
// one cheap barrier) with 256-bit vector memory ops (sm_10x LDG.E.256 /
// STG.E.256): 3 loads + 1 store per thread instead of 6 + 2.

#define NB          4194304
#define NS          8
#define BPL         524288                   // buckets in last layer
#define NTHREADS    256
#define BPB         256                      // buckets per block (1 per thread)
#define NWARPS      (NTHREADS / 32)          // 8
#define NGRID       (NB / BPB)               // 16384
#define FIRST_LAST  ((NB - BPL) / BPB)       // 14336
#define NLASTBLK    (BPL / BPB)              // 2048
#define OUT_SQ_OFF  NB
#define OUT_SCALAR  (NB * (NS + 1))          // 37748736

__device__ double   g_partials[NLASTBLK];
__device__ unsigned g_count = 0;

struct v8 { float x0,x1,x2,x3,x4,x5,x6,x7; };

__device__ __forceinline__ v8 ldcs_v8(const float* p) {
    v8 r;
    asm volatile("ld.global.cs.v8.b32 {%0,%1,%2,%3,%4,%5,%6,%7}, [%8];"
        : "=f"(r.x0), "=f"(r.x1), "=f"(r.x2), "=f"(r.x3),
          "=f"(r.x4), "=f"(r.x5), "=f"(r.x6), "=f"(r.x7)
        : "l"(p));
    return r;
}

__device__ __forceinline__ void stcs_v8(float* p, float a0, float a1, float a2, float a3,
                                                  float a4, float a5, float a6, float a7) {
    asm volatile("st.global.cs.v8.b32 [%0], {%1,%2,%3,%4,%5,%6,%7,%8};"
        :: "l"(p),
           "f"(a0), "f"(a1), "f"(a2), "f"(a3),
           "f"(a4), "f"(a5), "f"(a6), "f"(a7)
        : "memory");
}

// q = theta * sqrt(2*9.8*h) * 0.5*(tanh(h)+1) * area,  h = max(0, H - height)
// 0.5*(tanh(h)+1) == sigmoid(2h) == 1/(1+exp(-2h))  -> EX2 + RCP (err ~1e-7)
__device__ __forceinline__ float spigot_q(float Hb, float sh, float sa, float th) {
    float h = fmaxf(0.0f, Hb - sh);
    float e = __expf(-2.0f * h);
    float mod;
    asm("rcp.approx.f32 %0, %1;" : "=f"(mod) : "f"(1.0f + e));
    float s;
    asm("sqrt.approx.f32 %0, %1;" : "=f"(s) : "f"(19.6f * h));
    return th * s * mod * sa;
}

__global__ __launch_bounds__(NTHREADS)
void nash_main(const float* __restrict__ H,
               const float* __restrict__ S,      // [NB*16]
               const float* __restrict__ T,      // [NB*8]
               const float* __restrict__ precip,
               float* __restrict__ out)
{
    float* Hn = out;
    float* SQ = out + OUT_SQ_OFF;

    const int tid  = threadIdx.x;
    const int lane = tid & 31;
    const int warp = tid >> 5;
    const int b    = blockIdx.x * BPB + tid;

    // ---- front-batched streaming loads: whole bucket in 3x256b + 1x32b ----
    const float Hb = H[b];
    const v8 sa = ldcs_v8(S + (size_t)b * 16);       // spigots 0-3 (h,a pairs)
    const v8 sb = ldcs_v8(S + (size_t)b * 16 + 8);   // spigots 4-7
    const v8 tv = ldcs_v8(T + (size_t)b * 8);        // theta 0-7

    // ---- block-boundary bucket (b0-1): warp 0, lanes 0-7, one spigot each ----
    float pe = 0.0f;
    if (warp == 0) {
        if (blockIdx.x != 0 && lane < 8) {
            const int    bp = blockIdx.x * BPB - 1;
            const float  Hp = H[bp];
            const float2 sp = ((const float2*)S)[(size_t)bp * 8 + lane];
            const float  tp = T[(size_t)bp * 8 + lane];
            pe = spigot_q(Hp, sp.x, sp.y, tp);
        }
        pe += __shfl_xor_sync(0xffffffffu, pe, 1);
        pe += __shfl_xor_sync(0xffffffffu, pe, 2);
        pe += __shfl_xor_sync(0xffffffffu, pe, 4);   // lane 0 = full sum
    }

    // ---- 8 spigots, all in-register ----
    const float q0 = spigot_q(Hb, sa.x0, sa.x1, tv.x0);
    const float q1 = spigot_q(Hb, sa.x2, sa.x3, tv.x1);
    const float q2 = spigot_q(Hb, sa.x4, sa.x5, tv.x2);
    const float q3 = spigot_q(Hb, sa.x6, sa.x7, tv.x3);
    const float q4 = spigot_q(Hb, sb.x0, sb.x1, tv.x4);
    const float q5 = spigot_q(Hb, sb.x2, sb.x3, tv.x5);
    const float q6 = spigot_q(Hb, sb.x4, sb.x5, tv.x6);
    const float q7 = spigot_q(Hb, sb.x6, sb.x7, tv.x7);

    stcs_v8(SQ + (size_t)b * 8, q0, q1, q2, q3, q4, q5, q6, q7);

    const float ob = ((q0 + q1) + (q2 + q3)) + ((q4 + q5) + (q6 + q7));

    // ---- inflow[b] = outflow[b-1]: shfl_up + smem warp carries ----
    float inflow = __shfl_up_sync(0xffffffffu, ob, 1);
    __shared__ float s_carry[NWARPS];
    if (lane == 31) s_carry[warp] = ob;
    __syncthreads();
    if (lane == 0)
        inflow = (warp == 0)
               ? ((blockIdx.x == 0) ? __ldg(precip) : pe)
               : s_carry[warp - 1];
    __stcs(&Hn[b], Hb + inflow - ob);

    // ---- last-layer network-outflow reduction (last 12.5% of blocks) ----
    if (blockIdx.x >= FIRST_LAST) {
        double a = (double)ob;
        a += __shfl_xor_sync(0xffffffffu, a, 16);
        a += __shfl_xor_sync(0xffffffffu, a, 8);
        a += __shfl_xor_sync(0xffffffffu, a, 4);
        a += __shfl_xor_sync(0xffffffffu, a, 2);
        a += __shfl_xor_sync(0xffffffffu, a, 1);

        __shared__ double sd[NWARPS];
        __shared__ bool   s_last;
        if (tid == 0) s_last = false;
        if (lane == 0) sd[warp] = a;
        __syncthreads();
        if (tid == 0) {
            double bs = ((sd[0] + sd[1]) + (sd[2] + sd[3]))
                      + ((sd[4] + sd[5]) + (sd[6] + sd[7]));
            g_partials[blockIdx.x - FIRST_LAST] = bs;
            __threadfence();
            unsigned t = atomicAdd(&g_count, 1u);
            if (t == NLASTBLK - 1) s_last = true;
        }
        __syncthreads();

        if (s_last) {
            // Last block alive: fixed-order reduction (bit-deterministic).
            __threadfence();
            double acc = 0.0;
            #pragma unroll 4
            for (int i = tid; i < NLASTBLK; i += NTHREADS)
                acc += g_partials[i];
            __shared__ double sm[NTHREADS];
            sm[tid] = acc;
            __syncthreads();
            #pragma unroll
            for (int s = NTHREADS / 2; s > 0; s >>= 1) {
                if (tid < s) sm[tid] += sm[tid + s];
                __syncthreads();
            }
            if (tid == 0) {
                out[OUT_SCALAR] = (float)sm[0];
                g_count = 0;                     // reset for graph replay
            }
        }
    }
}

extern "C" void kernel_launch(void* const* d_in, const int* in_sizes, int n_in,
                              void* d_out, int out_size) {
    const float* H      = (const float*)d_in[0];
    const float* S      = (const float*)d_in[1];
    const float* T      = (const float*)d_in[2];
    const float* precip = (const float*)d_in[3];

    nash_main<<<NGRID, NTHREADS>>>(H, S, T, precip, (float*)d_out);
}

// round 15
// speedup vs baseline: 1.0441x; 1.0029x over previous
#include <cuda_runtime.h>

// NashCascadeNetwork: 8 layers x 524288 buckets, 8 spigots/bucket.
// Inputs (metadata order): H[NB] f32, S[NB,8,2] f32, theta[NB*8] f32, precip[1] f32
// Output (f32): [ H_new(NB) | s_q(NB*8) | network_outflow(1) ]
//
// R14 (v8 256-bit memory ops) + 2 buckets per thread: 128-thread blocks,
// block owns 256 buckets; thread tid owns local buckets tid and tid+128.
// 6 front-batched LDG.256 per thread -> double per-thread MLP.

#define NB          4194304
#define NS          8
#define BPL         524288                   // buckets in last layer
#define NTHREADS    128
#define BPB         256                      // buckets per block (2 per thread)
#define NWARPS      (NTHREADS / 32)          // 4
#define NGRID       (NB / BPB)               // 16384
#define FIRST_LAST  ((NB - BPL) / BPB)       // 14336
#define NLASTBLK    (BPL / BPB)              // 2048
#define OUT_SQ_OFF  NB
#define OUT_SCALAR  (NB * (NS + 1))          // 37748736

__device__ double   g_partials[NLASTBLK];
__device__ unsigned g_count = 0;

struct v8 { float x0,x1,x2,x3,x4,x5,x6,x7; };

__device__ __forceinline__ v8 ldcs_v8(const float* p) {
    v8 r;
    asm volatile("ld.global.cs.v8.b32 {%0,%1,%2,%3,%4,%5,%6,%7}, [%8];"
        : "=f"(r.x0), "=f"(r.x1), "=f"(r.x2), "=f"(r.x3),
          "=f"(r.x4), "=f"(r.x5), "=f"(r.x6), "=f"(r.x7)
        : "l"(p));
    return r;
}

__device__ __forceinline__ void stcs_v8(float* p, float a0, float a1, float a2, float a3,
                                                  float a4, float a5, float a6, float a7) {
    asm volatile("st.global.cs.v8.b32 [%0], {%1,%2,%3,%4,%5,%6,%7,%8};"
        :: "l"(p),
           "f"(a0), "f"(a1), "f"(a2), "f"(a3),
           "f"(a4), "f"(a5), "f"(a6), "f"(a7)
        : "memory");
}

// q = theta * sqrt(2*9.8*h) * 0.5*(tanh(h)+1) * area,  h = max(0, H - height)
// 0.5*(tanh(h)+1) == sigmoid(2h) == 1/(1+exp(-2h))  -> EX2 + RCP (err ~1e-7)
__device__ __forceinline__ float spigot_q(float Hb, float sh, float sa, float th) {
    float h = fmaxf(0.0f, Hb - sh);
    float e = __expf(-2.0f * h);
    float mod;
    asm("rcp.approx.f32 %0, %1;" : "=f"(mod) : "f"(1.0f + e));
    float s;
    asm("sqrt.approx.f32 %0, %1;" : "=f"(s) : "f"(19.6f * h));
    return th * s * mod * sa;
}

__global__ __launch_bounds__(NTHREADS)
void nash_main(const float* __restrict__ H,
               const float* __restrict__ S,      // [NB*16]
               const float* __restrict__ T,      // [NB*8]
               const float* __restrict__ precip,
               float* __restrict__ out)
{
    float* Hn = out;
    float* SQ = out + OUT_SQ_OFF;

    const int tid  = threadIdx.x;
    const int lane = tid & 31;
    const int warp = tid >> 5;
    const int b1   = blockIdx.x * BPB + tid;
    const int b2   = b1 + NTHREADS;

    // ---- front-batched streaming loads: 2 buckets = 6x256b + 2x32b ----
    const float H1 = H[b1];
    const float H2 = H[b2];
    const v8 sa1 = ldcs_v8(S + (size_t)b1 * 16);
    const v8 sb1 = ldcs_v8(S + (size_t)b1 * 16 + 8);
    const v8 tv1 = ldcs_v8(T + (size_t)b1 * 8);
    const v8 sa2 = ldcs_v8(S + (size_t)b2 * 16);
    const v8 sb2 = ldcs_v8(S + (size_t)b2 * 16 + 8);
    const v8 tv2 = ldcs_v8(T + (size_t)b2 * 8);

    // ---- block-boundary bucket (b0-1): warp 0, lanes 0-7, one spigot each ----
    float pe = 0.0f;
    if (warp == 0) {
        if (blockIdx.x != 0 && lane < 8) {
            const int    bp = blockIdx.x * BPB - 1;
            const float  Hp = H[bp];
            const float2 sp = ((const float2*)S)[(size_t)bp * 8 + lane];
            const float  tp = T[(size_t)bp * 8 + lane];
            pe = spigot_q(Hp, sp.x, sp.y, tp);
        }
        pe += __shfl_xor_sync(0xffffffffu, pe, 1);
        pe += __shfl_xor_sync(0xffffffffu, pe, 2);
        pe += __shfl_xor_sync(0xffffffffu, pe, 4);   // lane 0 = full sum
    }

    // ---- bucket 1: 8 spigots in-register ----
    const float q10 = spigot_q(H1, sa1.x0, sa1.x1, tv1.x0);
    const float q11 = spigot_q(H1, sa1.x2, sa1.x3, tv1.x1);
    const float q12 = spigot_q(H1, sa1.x4, sa1.x5, tv1.x2);
    const float q13 = spigot_q(H1, sa1.x6, sa1.x7, tv1.x3);
    const float q14 = spigot_q(H1, sb1.x0, sb1.x1, tv1.x4);
    const float q15 = spigot_q(H1, sb1.x2, sb1.x3, tv1.x5);
    const float q16 = spigot_q(H1, sb1.x4, sb1.x5, tv1.x6);
    const float q17 = spigot_q(H1, sb1.x6, sb1.x7, tv1.x7);
    stcs_v8(SQ + (size_t)b1 * 8, q10, q11, q12, q13, q14, q15, q16, q17);
    const float ob1 = ((q10 + q11) + (q12 + q13)) + ((q14 + q15) + (q16 + q17));

    // ---- bucket 2: 8 spigots in-register ----
    const float q20 = spigot_q(H2, sa2.x0, sa2.x1, tv2.x0);
    const float q21 = spigot_q(H2, sa2.x2, sa2.x3, tv2.x1);
    const float q22 = spigot_q(H2, sa2.x4, sa2.x5, tv2.x2);
    const float q23 = spigot_q(H2, sa2.x6, sa2.x7, tv2.x3);
    const float q24 = spigot_q(H2, sb2.x0, sb2.x1, tv2.x4);
    const float q25 = spigot_q(H2, sb2.x2, sb2.x3, tv2.x5);
    const float q26 = spigot_q(H2, sb2.x4, sb2.x5, tv2.x6);
    const float q27 = spigot_q(H2, sb2.x6, sb2.x7, tv2.x7);
    stcs_v8(SQ + (size_t)b2 * 8, q20, q21, q22, q23, q24, q25, q26, q27);
    const float ob2 = ((q20 + q21) + (q22 + q23)) + ((q24 + q25) + (q26 + q27));

    // ---- inflow[b] = outflow[b-1] for both sets: shfl_up + smem carries ----
    float in1 = __shfl_up_sync(0xffffffffu, ob1, 1);
    float in2 = __shfl_up_sync(0xffffffffu, ob2, 1);
    __shared__ float c1[NWARPS], c2[NWARPS];
    if (lane == 31) { c1[warp] = ob1; c2[warp] = ob2; }
    __syncthreads();
    if (lane == 0) {
        in1 = (warp == 0)
            ? ((blockIdx.x == 0) ? __ldg(precip) : pe)
            : c1[warp - 1];
        // predecessor of local bucket 128 is local bucket 127 = c1[3]
        in2 = (warp == 0) ? c1[NWARPS - 1] : c2[warp - 1];
    }
    __stcs(&Hn[b1], H1 + in1 - ob1);
    __stcs(&Hn[b2], H2 + in2 - ob2);

    // ---- last-layer network-outflow reduction (last 12.5% of blocks) ----
    if (blockIdx.x >= FIRST_LAST) {
        double a = (double)ob1 + (double)ob2;
        a += __shfl_xor_sync(0xffffffffu, a, 16);
        a += __shfl_xor_sync(0xffffffffu, a, 8);
        a += __shfl_xor_sync(0xffffffffu, a, 4);
        a += __shfl_xor_sync(0xffffffffu, a, 2);
        a += __shfl_xor_sync(0xffffffffu, a, 1);

        __shared__ double sd[NWARPS];
        __shared__ bool   s_last;
        if (tid == 0) s_last = false;
        if (lane == 0) sd[warp] = a;
        __syncthreads();
        if (tid == 0) {
            double bs = ((sd[0] + sd[1]) + (sd[2] + sd[3]));
            g_partials[blockIdx.x - FIRST_LAST] = bs;
            __threadfence();
            unsigned t = atomicAdd(&g_count, 1u);
            if (t == NLASTBLK - 1) s_last = true;
        }
        __syncthreads();

        if (s_last) {
            // Last block alive: fixed-order reduction (bit-deterministic).
            __threadfence();
            double acc = 0.0;
            #pragma unroll 4
            for (int i = tid; i < NLASTBLK; i += NTHREADS)
                acc += g_partials[i];
            __shared__ double sm[NTHREADS];
            sm[tid] = acc;
            __syncthreads();
            #pragma unroll
            for (int s = NTHREADS / 2; s > 0; s >>= 1) {
                if (tid < s) sm[tid] += sm[tid + s];
                __syncthreads();
            }
            if (tid == 0) {
                out[OUT_SCALAR] = (float)sm[0];
                g_count = 0;                     // reset for graph replay
            }
        }
    }
}

extern "C" void kernel_launch(void* const* d_in, const int* in_sizes, int n_in,
                              void* d_out, int out_size) {
    const float* H      = (const float*)d_in[0];
    const float* S      = (const float*)d_in[1];
    const float* T      = (const float*)d_in[2];
    const float* precip = (const float*)d_in[3];

    nash_main<<<NGRID, NTHREADS>>>(H, S, T, precip, (float*)d_out);
}

// round 16
// speedup vs baseline: 1.0486x; 1.0044x over previous
#include <cuda_runtime.h>

// NashCascadeNetwork: 8 layers x 524288 buckets, 8 spigots/bucket.
// Inputs (metadata order): H[NB] f32, S[NB,8,2] f32, theta[NB*8] f32, precip[1] f32
// Output (f32): [ H_new(NB) | s_q(NB*8) | network_outflow(1) ]
//
// v8 256-bit memory ops + 4 buckets per thread: 128-thread blocks own 512
// buckets; thread tid owns local buckets tid, tid+128, tid+256, tid+384.
// 12 front-batched LDG.256 per thread -> maximal per-thread MLP.

#define NB          4194304
#define NS          8
#define BPL         524288                   // buckets in last layer
#define NTHREADS    128
#define NSETS       4
#define BPB         512                      // buckets per block (4 per thread)
#define NWARPS      (NTHREADS / 32)          // 4
#define NGRID       (NB / BPB)               // 8192
#define FIRST_LAST  ((NB - BPL) / BPB)       // 7168
#define NLASTBLK    (BPL / BPB)              // 1024
#define OUT_SQ_OFF  NB
#define OUT_SCALAR  (NB * (NS + 1))          // 37748736

__device__ double   g_partials[NLASTBLK];
__device__ unsigned g_count = 0;

struct v8 { float x0,x1,x2,x3,x4,x5,x6,x7; };

__device__ __forceinline__ v8 ldcs_v8(const float* p) {
    v8 r;
    asm volatile("ld.global.cs.v8.b32 {%0,%1,%2,%3,%4,%5,%6,%7}, [%8];"
        : "=f"(r.x0), "=f"(r.x1), "=f"(r.x2), "=f"(r.x3),
          "=f"(r.x4), "=f"(r.x5), "=f"(r.x6), "=f"(r.x7)
        : "l"(p));
    return r;
}

__device__ __forceinline__ void stcs_v8(float* p, float a0, float a1, float a2, float a3,
                                                  float a4, float a5, float a6, float a7) {
    asm volatile("st.global.cs.v8.b32 [%0], {%1,%2,%3,%4,%5,%6,%7,%8};"
        :: "l"(p),
           "f"(a0), "f"(a1), "f"(a2), "f"(a3),
           "f"(a4), "f"(a5), "f"(a6), "f"(a7)
        : "memory");
}

// q = theta * sqrt(2*9.8*h) * 0.5*(tanh(h)+1) * area,  h = max(0, H - height)
// 0.5*(tanh(h)+1) == sigmoid(2h) == 1/(1+exp(-2h))  -> EX2 + RCP (err ~1e-7)
__device__ __forceinline__ float spigot_q(float Hb, float sh, float sa, float th) {
    float h = fmaxf(0.0f, Hb - sh);
    float e = __expf(-2.0f * h);
    float mod;
    asm("rcp.approx.f32 %0, %1;" : "=f"(mod) : "f"(1.0f + e));
    float s;
    asm("sqrt.approx.f32 %0, %1;" : "=f"(s) : "f"(19.6f * h));
    return th * s * mod * sa;
}

__global__ __launch_bounds__(NTHREADS)
void nash_main(const float* __restrict__ H,
               const float* __restrict__ S,      // [NB*16]
               const float* __restrict__ T,      // [NB*8]
               const float* __restrict__ precip,
               float* __restrict__ out)
{
    float* Hn = out;
    float* SQ = out + OUT_SQ_OFF;

    const int tid  = threadIdx.x;
    const int lane = tid & 31;
    const int warp = tid >> 5;
    const int base = blockIdx.x * BPB + tid;

    // ---- front-batched streaming loads: 4 buckets = 12x256b + 4x32b ----
    float Hv[NSETS];
    v8 sa[NSETS], sb[NSETS], tv[NSETS];
    #pragma unroll
    for (int k = 0; k < NSETS; k++) {
        const int b = base + k * NTHREADS;
        Hv[k] = H[b];
        sa[k] = ldcs_v8(S + (size_t)b * 16);
        sb[k] = ldcs_v8(S + (size_t)b * 16 + 8);
        tv[k] = ldcs_v8(T + (size_t)b * 8);
    }

    // ---- block-boundary bucket (b0-1): warp 0, lanes 0-7, one spigot each ----
    float pe = 0.0f;
    if (warp == 0) {
        if (blockIdx.x != 0 && lane < 8) {
            const int    bp = blockIdx.x * BPB - 1;
            const float  Hp = H[bp];
            const float2 sp = ((const float2*)S)[(size_t)bp * 8 + lane];
            const float  tp = T[(size_t)bp * 8 + lane];
            pe = spigot_q(Hp, sp.x, sp.y, tp);
        }
        pe += __shfl_xor_sync(0xffffffffu, pe, 1);
        pe += __shfl_xor_sync(0xffffffffu, pe, 2);
        pe += __shfl_xor_sync(0xffffffffu, pe, 4);   // lane 0 = full sum
    }

    // ---- 8 spigots per bucket, all in-register ----
    float ob[NSETS];
    #pragma unroll
    for (int k = 0; k < NSETS; k++) {
        const int b = base + k * NTHREADS;
        const float q0 = spigot_q(Hv[k], sa[k].x0, sa[k].x1, tv[k].x0);
        const float q1 = spigot_q(Hv[k], sa[k].x2, sa[k].x3, tv[k].x1);
        const float q2 = spigot_q(Hv[k], sa[k].x4, sa[k].x5, tv[k].x2);
        const float q3 = spigot_q(Hv[k], sa[k].x6, sa[k].x7, tv[k].x3);
        const float q4 = spigot_q(Hv[k], sb[k].x0, sb[k].x1, tv[k].x4);
        const float q5 = spigot_q(Hv[k], sb[k].x2, sb[k].x3, tv[k].x5);
        const float q6 = spigot_q(Hv[k], sb[k].x4, sb[k].x5, tv[k].x6);
        const float q7 = spigot_q(Hv[k], sb[k].x6, sb[k].x7, tv[k].x7);
        stcs_v8(SQ + (size_t)b * 8, q0, q1, q2, q3, q4, q5, q6, q7);
        ob[k] = ((q0 + q1) + (q2 + q3)) + ((q4 + q5) + (q6 + q7));
    }

    // ---- inflow[b] = outflow[b-1]: shfl_up per set + smem warp carries ----
    __shared__ float c[NSETS][NWARPS];
    float in[NSETS];
    #pragma unroll
    for (int k = 0; k < NSETS; k++) {
        in[k] = __shfl_up_sync(0xffffffffu, ob[k], 1);
        if (lane == 31) c[k][warp] = ob[k];
    }
    __syncthreads();
    if (lane == 0) {
        #pragma unroll
        for (int k = 0; k < NSETS; k++) {
            if (warp == 0)
                in[k] = (k == 0)
                      ? ((blockIdx.x == 0) ? __ldg(precip) : pe)
                      : c[k - 1][NWARPS - 1];   // local bucket k*128-1
            else
                in[k] = c[k][warp - 1];
        }
    }
    #pragma unroll
    for (int k = 0; k < NSETS; k++)
        __stcs(&Hn[base + k * NTHREADS], Hv[k] + in[k] - ob[k]);

    // ---- last-layer network-outflow reduction (last 12.5% of blocks) ----
    if (blockIdx.x >= FIRST_LAST) {
        double a = ((double)ob[0] + (double)ob[1])
                 + ((double)ob[2] + (double)ob[3]);
        a += __shfl_xor_sync(0xffffffffu, a, 16);
        a += __shfl_xor_sync(0xffffffffu, a, 8);
        a += __shfl_xor_sync(0xffffffffu, a, 4);
        a += __shfl_xor_sync(0xffffffffu, a, 2);
        a += __shfl_xor_sync(0xffffffffu, a, 1);

        __shared__ double sd[NWARPS];
        __shared__ bool   s_last;
        if (tid == 0) s_last = false;
        if (lane == 0) sd[warp] = a;
        __syncthreads();
        if (tid == 0) {
            double bs = ((sd[0] + sd[1]) + (sd[2] + sd[3]));
            g_partials[blockIdx.x - FIRST_LAST] = bs;
            __threadfence();
            unsigned t = atomicAdd(&g_count, 1u);
            if (t == NLASTBLK - 1) s_last = true;
        }
        __syncthreads();

        if (s_last) {
            // Last block alive: fixed-order reduction (bit-deterministic).
            __threadfence();
            double acc = 0.0;
            #pragma unroll 4
            for (int i = tid; i < NLASTBLK; i += NTHREADS)
                acc += g_partials[i];
            __shared__ double sm[NTHREADS];
            sm[tid] = acc;
            __syncthreads();
            #pragma unroll
            for (int s = NTHREADS / 2; s > 0; s >>= 1) {
                if (tid < s) sm[tid] += sm[tid + s];
                __syncthreads();
            }
            if (tid == 0) {
                out[OUT_SCALAR] = (float)sm[0];
                g_count = 0;                     // reset for graph replay
            }
        }
    }
}

extern "C" void kernel_launch(void* const* d_in, const int* in_sizes, int n_in,
                              void* d_out, int out_size) {
    const float* H      = (const float*)d_in[0];
    const float* S      = (const float*)d_in[1];
    const float* T      = (const float*)d_in[2];
    const float* precip = (const float*)d_in[3];

    nash_main<<<NGRID, NTHREADS>>>(H, S, T, precip, (float*)d_out);
}